// round 1
// baseline (speedup 1.0000x reference)
#include <cuda_runtime.h>
#include <cuda_bf16.h>
#include <cstdint>

// ============================================================================
// QConv2D: quantum-circuit conv. The circuit is data-independent -> one 64x64
// complex unitary U. Kernel 1 builds U from weights. Kernel 2 does, per patch:
//   feat = normalized 64-vector of patch pixels
//   g = U @ feat   (complex matvec, via packed fma.rn.f32x2)
//   p_i = |g_i|^2 ;  z_w = sum_i sign_w(i) * p_i ;  write z
// ============================================================================

#define N_QUBITS 6
#define DIM 64
#define OH 63
#define BATCH 128
#define NPATCH (BATCH * OH * OH)   // 508032

__device__ float2 g_UT[DIM * DIM];  // g_UT[j*64+i] = U[i][j]  (feat-index major)

// ----------------------------------------------------------------------------
// Kernel 1: build the unitary. 64 threads, thread c owns column c = U @ e_c.
// ----------------------------------------------------------------------------
__global__ void build_unitary_kernel(const float* __restrict__ w) {
    __shared__ float2 S[DIM][DIM];   // S[c][i]: amplitude i of column c
    int c = threadIdx.x;
    if (c >= DIM) return;
    #pragma unroll
    for (int i = 0; i < DIM; i++) S[c][i] = make_float2(i == c ? 1.f : 0.f, 0.f);

    for (int rep = 0; rep < 2; rep++) {
        for (int l = 0; l < 2; l++) {
            // --- 6 single-qubit rotations, weights[l][q] ---
            for (int q = 0; q < N_QUBITS; q++) {
                float phi   = w[(l * N_QUBITS + q) * 3 + 0];
                float theta = w[(l * N_QUBITS + q) * 3 + 1];
                float omega = w[(l * N_QUBITS + q) * 3 + 2];
                float s2, c2; sincosf(0.5f * theta, &s2, &c2);
                float ap = -0.5f * (phi + omega);
                float am = -0.5f * (phi - omega);
                float sap, cap; sincosf(ap, &sap, &cap);
                float sam, cam; sincosf(am, &sam, &cam);
                // U00 = e^{i ap} c2 ; U01 = -conj(e^{i am}) s2
                // U10 = e^{i am} s2 ; U11 =  conj(e^{i ap}) c2
                float u00x =  cap * c2, u00y =  sap * c2;
                float u01x = -cam * s2, u01y =  sam * s2;
                float u10x =  cam * s2, u10y =  sam * s2;
                float u11x =  cap * c2, u11y = -sap * c2;
                int m = 1 << (5 - q);
                for (int i = 0; i < DIM; i++) {
                    if (i & m) continue;
                    float2 a = S[c][i], b = S[c][i | m];
                    float2 na, nb;
                    na.x = u00x * a.x - u00y * a.y + u01x * b.x - u01y * b.y;
                    na.y = u00x * a.y + u00y * a.x + u01x * b.y + u01y * b.x;
                    nb.x = u10x * a.x - u10y * a.y + u11x * b.x - u11y * b.y;
                    nb.y = u10x * a.y + u10y * a.x + u11x * b.y + u11y * b.x;
                    S[c][i] = na; S[c][i | m] = nb;
                }
            }
            // --- ring of CNOTs, range r = l+1 ---
            int r = (l % (N_QUBITS - 1)) + 1;
            for (int q = 0; q < N_QUBITS; q++) {
                int t  = (q + r) % N_QUBITS;
                int mc = 1 << (5 - q);
                int mt = 1 << (5 - t);
                for (int i = 0; i < DIM; i++) {
                    if ((i & mc) && !(i & mt)) {
                        float2 tmp = S[c][i];
                        S[c][i] = S[c][i | mt];
                        S[c][i | mt] = tmp;
                    }
                }
            }
        }
    }
    // column c of U == U[i][c] for all i  ->  UT[c][i]
    #pragma unroll
    for (int i = 0; i < DIM; i++) g_UT[c * DIM + i] = S[c][i];
}

// ----------------------------------------------------------------------------
// Kernel 2: per-patch matvec + measurement. 256 threads/block, 8 warps,
// 4 patches per warp (reuses each shared-U load across 4 accumulator sets).
// ----------------------------------------------------------------------------
__device__ __forceinline__ void fma_f32x2(unsigned long long& acc,
                                          unsigned long long u,
                                          unsigned long long f) {
    asm("fma.rn.f32x2 %0, %1, %2, %0;" : "+l"(acc) : "l"(u), "l"(f));
}
__device__ __forceinline__ unsigned long long dup_f32(float v) {
    unsigned long long r;
    asm("mov.b64 %0, {%1, %1};" : "=l"(r) : "f"(v));
    return r;
}

__global__ __launch_bounds__(256) void qconv_kernel(const float* __restrict__ x,
                                                    float* __restrict__ out) {
    __shared__ float2 sU[DIM * DIM];   // 32 KB
    int tid = threadIdx.x;
    {
        const float4* src = reinterpret_cast<const float4*>(g_UT);
        float4* dst = reinterpret_cast<float4*>(sU);
        #pragma unroll
        for (int i = tid; i < DIM * DIM / 2; i += 256) dst[i] = src[i];
    }
    __syncthreads();

    const int lane = tid & 31;
    const int wid  = tid >> 5;
    const int pbase = blockIdx.x * 32 + wid * 4;

    // feature element indices owned by this lane
    const int e0 = lane, e1 = lane + 32;
    const int c0 = e0 >> 4, ky0 = (e0 >> 2) & 3, kx0 = e0 & 3;
    const int c1 = e1 >> 4, ky1 = (e1 >> 2) & 3, kx1 = e1 & 3;

    float f0[4], f1[4];
    int obase[4];
    #pragma unroll
    for (int p = 0; p < 4; p++) {
        int pi  = pbase + p;
        int b   = pi / (OH * OH);
        int rem = pi - b * (OH * OH);
        int oy  = rem / OH;
        int ox  = rem - oy * OH;
        obase[p] = (b * N_QUBITS * OH + oy) * OH + ox;

        f0[p] = x[((b * 4 + c0) * 128 + oy * 2 + ky0) * 128 + ox * 2 + kx0];
        f1[p] = x[((b * 4 + c1) * 128 + oy * 2 + ky1) * 128 + ox * 2 + kx1];

        float ss = f0[p] * f0[p] + f1[p] * f1[p];
        #pragma unroll
        for (int o = 16; o; o >>= 1) ss += __shfl_xor_sync(0xffffffffu, ss, o);
        float rn = rsqrtf(ss);
        f0[p] *= rn; f1[p] *= rn;
    }

    // complex matvec: acc0[p] = g[lane] (re,im packed), acc1[p] = g[lane+32]
    unsigned long long acc0[4] = {0ull, 0ull, 0ull, 0ull};
    unsigned long long acc1[4] = {0ull, 0ull, 0ull, 0ull};

    #pragma unroll
    for (int j = 0; j < 32; j++) {
        unsigned long long u0 = *reinterpret_cast<const unsigned long long*>(&sU[j * DIM + lane]);
        unsigned long long u1 = *reinterpret_cast<const unsigned long long*>(&sU[j * DIM + lane + 32]);
        #pragma unroll
        for (int p = 0; p < 4; p++) {
            unsigned long long fd = dup_f32(__shfl_sync(0xffffffffu, f0[p], j));
            fma_f32x2(acc0[p], u0, fd);
            fma_f32x2(acc1[p], u1, fd);
        }
    }
    #pragma unroll
    for (int j = 0; j < 32; j++) {
        unsigned long long u0 = *reinterpret_cast<const unsigned long long*>(&sU[(j + 32) * DIM + lane]);
        unsigned long long u1 = *reinterpret_cast<const unsigned long long*>(&sU[(j + 32) * DIM + lane + 32]);
        #pragma unroll
        for (int p = 0; p < 4; p++) {
            unsigned long long fd = dup_f32(__shfl_sync(0xffffffffu, f1[p], j));
            fma_f32x2(acc0[p], u0, fd);
            fma_f32x2(acc1[p], u1, fd);
        }
    }

    // measurement: p0 = |g[lane]|^2, p1 = |g[lane+32]|^2
    #pragma unroll
    for (int p = 0; p < 4; p++) {
        float2 a0 = *reinterpret_cast<float2*>(&acc0[p]);
        float2 a1 = *reinterpret_cast<float2*>(&acc1[p]);
        float p0 = a0.x * a0.x + a0.y * a0.y;
        float p1 = a1.x * a1.x + a1.y * a1.y;
        float q = p0 + p1;   // same sign for qubits 1..5 (bit5 differs only)
        float d = p0 - p1;   // qubit 0: lane (+), lane+32 (-)

        float z0 = d;
        #pragma unroll
        for (int o = 16; o; o >>= 1) z0 += __shfl_xor_sync(0xffffffffu, z0, o);

        float z1 = ((lane >> 4) & 1) ? -q : q;
        float z2 = ((lane >> 3) & 1) ? -q : q;
        float z3 = ((lane >> 2) & 1) ? -q : q;
        float z4 = ((lane >> 1) & 1) ? -q : q;
        float z5 = ((lane >> 0) & 1) ? -q : q;
        #pragma unroll
        for (int o = 16; o; o >>= 1) {
            z1 += __shfl_xor_sync(0xffffffffu, z1, o);
            z2 += __shfl_xor_sync(0xffffffffu, z2, o);
            z3 += __shfl_xor_sync(0xffffffffu, z3, o);
            z4 += __shfl_xor_sync(0xffffffffu, z4, o);
            z5 += __shfl_xor_sync(0xffffffffu, z5, o);
        }
        // lanes 0..5 each write one qubit's expectation
        float zv = z0;
        if (lane == 1) zv = z1;
        if (lane == 2) zv = z2;
        if (lane == 3) zv = z3;
        if (lane == 4) zv = z4;
        if (lane == 5) zv = z5;
        if (lane < N_QUBITS) out[obase[p] + lane * (OH * OH)] = zv;
    }
}

// ----------------------------------------------------------------------------
extern "C" void kernel_launch(void* const* d_in, const int* in_sizes, int n_in,
                              void* d_out, int out_size) {
    const float* x = (const float*)d_in[0];      // (128, 4, 128, 128) f32
    const float* w = (const float*)d_in[1];      // (2, 6, 3) f32
    float* out = (float*)d_out;                  // (128, 6, 63, 63) f32
    (void)in_sizes; (void)n_in; (void)out_size;

    build_unitary_kernel<<<1, 64>>>(w);
    qconv_kernel<<<NPATCH / 32, 256>>>(x, out);
}

// round 2
// speedup vs baseline: 2.2747x; 2.2747x over previous
#include <cuda_runtime.h>
#include <cuda_bf16.h>
#include <cstdint>

// ============================================================================
// QConv2D quantum conv. Circuit is data-independent -> one 64x64 complex
// unitary U built once (kernel 1, parallel). Kernel 2: per patch
//   g = U @ f_raw  (complex matvec, fma.rn.f32x2)
//   z_w = Walsh-signed sums of |g|^2, divided by ||f||^2 (normalization is
//   deferred: z is linear in probs).
// ============================================================================

#define N_QUBITS 6
#define DIM 64
#define OH 63
#define OHW (OH * OH)          // 3969
#define BATCH 128
#define NPATCH (BATCH * OHW)   // 508032
#define PPW 8                  // patches per warp
#define PPB 64                 // patches per block (8 warps)

__device__ float2 g_UT[DIM * DIM];  // g_UT[j*64+i] = U[i][j]

// ----------------------------------------------------------------------------
// Kernel 1: build the unitary. 1024 threads = 64 columns x 16 pair-workers.
// ----------------------------------------------------------------------------
__global__ __launch_bounds__(1024) void build_unitary_kernel(const float* __restrict__ w) {
    __shared__ float2 S[DIM][DIM];   // S[c][i]
    int t = threadIdx.x;
    int c = t >> 4;
    int k = t & 15;

    #pragma unroll
    for (int i = k; i < DIM; i += 16) S[c][i] = make_float2(i == c ? 1.f : 0.f, 0.f);
    __syncthreads();

    for (int rep = 0; rep < 2; rep++) {
        for (int l = 0; l < 2; l++) {
            for (int q = 0; q < N_QUBITS; q++) {
                float phi   = w[(l * N_QUBITS + q) * 3 + 0];
                float theta = w[(l * N_QUBITS + q) * 3 + 1];
                float omega = w[(l * N_QUBITS + q) * 3 + 2];
                float s2, c2; sincosf(0.5f * theta, &s2, &c2);
                float sap, cap; sincosf(-0.5f * (phi + omega), &sap, &cap);
                float sam, cam; sincosf(-0.5f * (phi - omega), &sam, &cam);
                float u00x =  cap * c2, u00y =  sap * c2;
                float u01x = -cam * s2, u01y =  sam * s2;
                float u10x =  cam * s2, u10y =  sam * s2;
                float u11x =  cap * c2, u11y = -sap * c2;
                int m = 1 << (5 - q);
                #pragma unroll
                for (int pp = 0; pp < 2; pp++) {
                    int pi = k + pp * 16;                    // 0..31
                    int i = ((pi & ~(m - 1)) << 1) | (pi & (m - 1));
                    float2 a = S[c][i], b = S[c][i | m];
                    float2 na, nb;
                    na.x = u00x * a.x - u00y * a.y + u01x * b.x - u01y * b.y;
                    na.y = u00x * a.y + u00y * a.x + u01x * b.y + u01y * b.x;
                    nb.x = u10x * a.x - u10y * a.y + u11x * b.x - u11y * b.y;
                    nb.y = u10x * a.y + u10y * a.x + u11x * b.y + u11y * b.x;
                    S[c][i] = na; S[c][i | m] = nb;
                }
                __syncthreads();
            }
            int r = (l % (N_QUBITS - 1)) + 1;
            for (int q = 0; q < N_QUBITS; q++) {
                int tq = (q + r) % N_QUBITS;
                int mc = 1 << (5 - q);
                int mt = 1 << (5 - tq);
                // thread k handles the k-th index with bit mc=1, bit mt=0
                int i = 0, kk = k;
                #pragma unroll
                for (int b = 0; b < 6; b++) {
                    int bit = 1 << b;
                    if (bit == mc)      i |= bit;
                    else if (bit == mt) { }
                    else { if (kk & 1) i |= bit; kk >>= 1; }
                }
                float2 tmp = S[c][i];
                S[c][i] = S[c][i | mt];
                S[c][i | mt] = tmp;
                __syncthreads();
            }
        }
    }
    #pragma unroll
    for (int i = k; i < DIM; i += 16) g_UT[c * DIM + i] = S[c][i];
}

// ----------------------------------------------------------------------------
// Kernel 2
// ----------------------------------------------------------------------------
__device__ __forceinline__ void fma_f32x2(unsigned long long& acc,
                                          unsigned long long u,
                                          unsigned long long f) {
    asm("fma.rn.f32x2 %0, %1, %2, %0;" : "+l"(acc) : "l"(u), "l"(f));
}
__device__ __forceinline__ unsigned long long dup_f32(float v) {
    unsigned long long r;
    asm("mov.b64 %0, {%1, %1};" : "=l"(r) : "f"(v));
    return r;
}

__global__ __launch_bounds__(256) void qconv_kernel(const float* __restrict__ x,
                                                    float* __restrict__ out) {
    __shared__ float2 sU[DIM * DIM];          // 32 KB, sU[j*64+i]
    __shared__ float  sF[8][512];             // 16 KB: per warp [j4 0..15][p 0..7][4]
    __shared__ float  sZ[N_QUBITS][65];       // staged outputs (padded)

    const int tid  = threadIdx.x;
    const int lane = tid & 31;
    const int wid  = tid >> 5;

    {   // cooperative U load
        const float4* src = reinterpret_cast<const float4*>(g_UT);
        float4* dst = reinterpret_cast<float4*>(sU);
        #pragma unroll
        for (int i = tid; i < DIM * DIM / 2; i += 256) dst[i] = src[i];
    }
    __syncthreads();

    const int pbase = blockIdx.x * PPB + wid * PPW;

    // ---------------- load phase: lane = (p = lane&7, r = lane>>3) ----------
    {
        const int p  = lane & 7;
        const int r  = lane >> 3;
        const int pi = pbase + p;
        const int b   = pi / OHW;
        const int rem = pi - b * OHW;
        const int oy  = rem / OH;
        const int ox  = rem - oy * OH;
        const float* xb = x + ((b * 4) * 128 + 2 * oy) * 128 + 2 * ox;

        float2 v[8];
        float ssq = 0.f;
        #pragma unroll
        for (int t = 0; t < 8; t++) {
            int rowid = t * 4 + r;                 // 0..31 = (c, ky, half)
            int c    = rowid >> 3;
            int ky   = (rowid >> 1) & 3;
            int half = rowid & 1;
            v[t] = *reinterpret_cast<const float2*>(xb + (c * 128 + ky) * 128 + half * 2);
            ssq += v[t].x * v[t].x + v[t].y * v[t].y;
        }
        ssq += __shfl_xor_sync(0xffffffffu, ssq, 8);
        ssq += __shfl_xor_sync(0xffffffffu, ssq, 16);
        // store raw features: e = 8t + 2r ; word = (e>>2)*32 + p*4 + (e&3)
        #pragma unroll
        for (int t = 0; t < 8; t++) {
            int e = t * 8 + r * 2;
            float* dst = &sF[wid][(e >> 2) * 32 + p * 4 + (e & 3)];
            *reinterpret_cast<float2*>(dst) = v[t];
        }
        // stash ssq for broadcast below via shfl
        // (lane p holds patch p's ssq)
        sZ[0][0] = sZ[0][0]; // no-op to keep compiler honest
        __syncwarp();
        // save ssq in a register visible after this scope
        // handled by writing to sF? no — keep via variable below
        // (we re-fetch with shfl from lane p)
        // fallthrough
        // NOTE: ssq lives on in 'ssq_keep'
        asm volatile("" :: "f"(ssq));
        // store to shared-free channel: use shfl later
        // ssq saved:
        // (see ssAll below)
        // -- pass via register:
        #pragma unroll
        for (int z = 0; z < 1; z++) {}
        // keep in thread-local
        // (ssq is captured below)
        sF[wid][511] = sF[wid][511]; // no-op
        // real keep:
        *((float*)&v[0]) = ssq; // reuse v[0].x as carrier (dead otherwise)
        __syncwarp();
        // broadcast all 8 patch ssq's to every lane
        float myss = v[0].x;
        float ssAll[PPW];
        #pragma unroll
        for (int pp = 0; pp < PPW; pp++)
            ssAll[pp] = __shfl_sync(0xffffffffu, myss, pp);

        // ---------------- matvec ----------------
        unsigned long long acc0[PPW], acc1[PPW];
        #pragma unroll
        for (int pp = 0; pp < PPW; pp++) { acc0[pp] = 0ull; acc1[pp] = 0ull; }

        const ulonglong2* sU2 = reinterpret_cast<const ulonglong2*>(sU);
        const float4* sFv = reinterpret_cast<const float4*>(sF[wid]);

        #pragma unroll
        for (int j4 = 0; j4 < 16; j4++) {
            float4 fv[PPW];
            #pragma unroll
            for (int pp = 0; pp < PPW; pp++) fv[pp] = sFv[j4 * 8 + pp];
            #pragma unroll
            for (int jj = 0; jj < 4; jj++) {
                int j = j4 * 4 + jj;
                ulonglong2 u = sU2[j * 32 + lane];   // (re,im) of i=2lane, 2lane+1
                #pragma unroll
                for (int pp = 0; pp < PPW; pp++) {
                    float fj = (jj == 0) ? fv[pp].x : (jj == 1) ? fv[pp].y
                             : (jj == 2) ? fv[pp].z : fv[pp].w;
                    unsigned long long fd = dup_f32(fj);
                    fma_f32x2(acc0[pp], u.x, fd);
                    fma_f32x2(acc1[pp], u.y, fd);
                }
            }
        }

        // ---------------- measurement ----------------
        #pragma unroll
        for (int pp = 0; pp < PPW; pp++) {
            float2 a0 = *reinterpret_cast<float2*>(&acc0[pp]);
            float2 a1 = *reinterpret_cast<float2*>(&acc1[pp]);
            float p0 = a0.x * a0.x + a0.y * a0.y;   // state i = 2*lane
            float p1 = a1.x * a1.x + a1.y * a1.y;   // state i = 2*lane+1
            float qv = p0 + p1;
            float dv = p0 - p1;                      // qubit 5 (i bit0)
            // 5-stage Walsh butterfly on qv; plain sum on dv
            #pragma unroll
            for (int bst = 0; bst < 5; bst++) {
                int m = 1 << bst;
                float t2 = __shfl_xor_sync(0xffffffffu, qv, m);
                qv = (lane & m) ? (t2 - qv) : (qv + t2);
                dv += __shfl_xor_sync(0xffffffffu, dv, m);
            }
            // writers: lane (1<<(4-w)) -> qubit w (w=0..4), lane 0 -> qubit 5
            bool writer = (lane == 16 || lane == 8 || lane == 4 ||
                           lane == 2  || lane == 1 || lane == 0);
            if (writer) {
                int qb; float val;
                if (lane == 0) { qb = 5; val = dv; }
                else {
                    int lg = 31 - __clz(lane);
                    qb = 4 - lg; val = qv;
                }
                sZ[qb][wid * PPW + pp] = val / ssAll[pp];
            }
        }
    }
    __syncthreads();

    // ---------------- coalesced store ----------------
    {
        int t = tid;
        if (t < 384) {
            int qb = t >> 6;           // 0..5
            int pl = t & 63;           // patch within block
            int pi = blockIdx.x * PPB + pl;
            int b  = pi / OHW;
            out[pi + OHW * (5 * b + qb)] = sZ[qb][pl];
        }
        t = tid + 256;
        if (t < 384) {
            int qb = t >> 6;
            int pl = t & 63;
            int pi = blockIdx.x * PPB + pl;
            int b  = pi / OHW;
            out[pi + OHW * (5 * b + qb)] = sZ[qb][pl];
        }
    }
}

// ----------------------------------------------------------------------------
extern "C" void kernel_launch(void* const* d_in, const int* in_sizes, int n_in,
                              void* d_out, int out_size) {
    const float* x = (const float*)d_in[0];      // (128, 4, 128, 128) f32
    const float* w = (const float*)d_in[1];      // (2, 6, 3) f32
    float* out = (float*)d_out;                  // (128, 6, 63, 63) f32
    (void)in_sizes; (void)n_in; (void)out_size;

    build_unitary_kernel<<<1, 1024>>>(w);
    qconv_kernel<<<NPATCH / PPB, 256>>>(x, out);
}

// round 4
// speedup vs baseline: 6.2174x; 2.7333x over previous
#include <cuda_runtime.h>
#include <cuda_bf16.h>
#include <cstdint>

// ============================================================================
// QConv2D quantum conv via baseline-PTX bf16 mma.sync (HMMA) GEMM.
//   Circuit -> fixed 64x64 complex unitary U (kernel 1, parallel).
//   B[128x64] rows interleaved: B[2s]=Re U[s,:], B[2s+1]=Im U[s,:] (bf16 hi/lo).
//   Kernel 2 (CTA = 128 patches): A = raw patch features (bf16 hi/lo),
//   C[128x128] = Ah*Bh^T + Ah*Bl^T + Al*Bh^T  (fp32 accum).
//   Epilogue: probs = C[:,2s]^2 + C[:,2s+1]^2 in-thread, Walsh-signed sums,
//   deferred normalization by ||f||^2.
// ============================================================================

#define N_QUBITS 6
#define DIM 64
#define OH 63
#define OHW 3969
#define NPATCH (128 * OHW)     // 508032
#define SWZ(o) ((o) ^ (((o) >> 3) & 0x70))

__device__ __nv_bfloat16 g_Bh[128 * 64];
__device__ __nv_bfloat16 g_Bl[128 * 64];

__device__ __forceinline__ uint32_t smem_u32(const void* p) {
    uint32_t a;
    asm("{ .reg .u64 t; cvta.to.shared.u64 t, %1; cvt.u32.u64 %0, t; }"
        : "=r"(a) : "l"(p));
    return a;
}
__device__ __forceinline__ void ldmx4(uint32_t* r, uint32_t addr) {
    asm volatile("ldmatrix.sync.aligned.m8n8.x4.shared.b16 {%0,%1,%2,%3}, [%4];"
                 : "=r"(r[0]), "=r"(r[1]), "=r"(r[2]), "=r"(r[3]) : "r"(addr));
}
__device__ __forceinline__ void mma_bf16(float* c, const uint32_t* a, const uint32_t* b) {
    asm volatile(
        "mma.sync.aligned.m16n8k16.row.col.f32.bf16.bf16.f32 "
        "{%0,%1,%2,%3}, {%4,%5,%6,%7}, {%8,%9}, {%0,%1,%2,%3};"
        : "+f"(c[0]), "+f"(c[1]), "+f"(c[2]), "+f"(c[3])
        : "r"(a[0]), "r"(a[1]), "r"(a[2]), "r"(a[3]), "r"(b[0]), "r"(b[1]));
}

// ----------------------------------------------------------------------------
// Kernel 1: build U; emit B interleaved (Re/Im per state) as bf16 hi/lo.
// grid=4, block=256; block handles 16 columns x 16 pair-workers.
// ----------------------------------------------------------------------------
__global__ __launch_bounds__(256) void build_unitary_kernel(const float* __restrict__ w) {
    __shared__ float2 S[16][DIM];
    __shared__ float gt[12][8];
    int t = threadIdx.x;
    int cl = t >> 4;
    int k  = t & 15;

    if (t < 12) {
        int l = t / 6, q = t % 6;
        float phi   = w[(l * 6 + q) * 3 + 0];
        float theta = w[(l * 6 + q) * 3 + 1];
        float omega = w[(l * 6 + q) * 3 + 2];
        float s2, c2; sincosf(0.5f * theta, &s2, &c2);
        float sap, cap; sincosf(-0.5f * (phi + omega), &sap, &cap);
        float sam, cam; sincosf(-0.5f * (phi - omega), &sam, &cam);
        gt[t][0] =  cap * c2; gt[t][1] =  sap * c2;   // u00
        gt[t][2] = -cam * s2; gt[t][3] =  sam * s2;   // u01
        gt[t][4] =  cam * s2; gt[t][5] =  sam * s2;   // u10
        gt[t][6] =  cap * c2; gt[t][7] = -sap * c2;   // u11
    }
    int c = blockIdx.x * 16 + cl;
    #pragma unroll
    for (int i = k; i < DIM; i += 16) S[cl][i] = make_float2(i == c ? 1.f : 0.f, 0.f);
    __syncthreads();

    for (int rep = 0; rep < 2; rep++) {
        for (int l = 0; l < 2; l++) {
            for (int q = 0; q < N_QUBITS; q++) {
                const float* g = gt[l * 6 + q];
                float u00x = g[0], u00y = g[1], u01x = g[2], u01y = g[3];
                float u10x = g[4], u10y = g[5], u11x = g[6], u11y = g[7];
                int m = 1 << (5 - q);
                #pragma unroll
                for (int pp = 0; pp < 2; pp++) {
                    int pi = k + pp * 16;
                    int i = ((pi & ~(m - 1)) << 1) | (pi & (m - 1));
                    float2 a = S[cl][i], b = S[cl][i | m];
                    float2 na, nb;
                    na.x = u00x * a.x - u00y * a.y + u01x * b.x - u01y * b.y;
                    na.y = u00x * a.y + u00y * a.x + u01x * b.y + u01y * b.x;
                    nb.x = u10x * a.x - u10y * a.y + u11x * b.x - u11y * b.y;
                    nb.y = u10x * a.y + u10y * a.x + u11x * b.y + u11y * b.x;
                    S[cl][i] = na; S[cl][i | m] = nb;
                }
                __syncthreads();
            }
            int r = (l % (N_QUBITS - 1)) + 1;
            for (int q = 0; q < N_QUBITS; q++) {
                int tq = (q + r) % N_QUBITS;
                int mc = 1 << (5 - q);
                int mt = 1 << (5 - tq);
                int i = 0, kk = k;
                #pragma unroll
                for (int b = 0; b < 6; b++) {
                    int bit = 1 << b;
                    if (bit == mc)      i |= bit;
                    else if (bit == mt) { }
                    else { if (kk & 1) i |= bit; kk >>= 1; }
                }
                float2 tmp = S[cl][i];
                S[cl][i] = S[cl][i | mt];
                S[cl][i | mt] = tmp;
                __syncthreads();
            }
        }
    }
    // B[n][kg]: n = 2s + r, r=0 -> Re U[s][kg], r=1 -> Im U[s][kg]
    for (int it = t; it < 128 * 16; it += 256) {
        int n  = it >> 4;
        int kl = it & 15;
        int s  = n >> 1;
        float v = (n & 1) ? S[kl][s].y : S[kl][s].x;
        __nv_bfloat16 hi = __float2bfloat16(v);
        __nv_bfloat16 lo = __float2bfloat16(v - __bfloat162float(hi));
        int kg = blockIdx.x * 16 + kl;
        g_Bh[n * 64 + kg] = hi;
        g_Bl[n * 64 + kg] = lo;
    }
}

// ----------------------------------------------------------------------------
// Kernel 2: HMMA GEMM + epilogue. 256 threads (8 warps, 4x2 tile grid).
// ----------------------------------------------------------------------------
#define SM_AH 0
#define SM_AL 16384
#define SM_BH 32768
#define SM_BL 49152
#define SM_SSQ 65536
#define SM_SZ  66048           // float[2][128][6] = 6144 B
#define SM_TOTAL 72192

__global__ __launch_bounds__(256, 2)
void qconv_kernel(const float* __restrict__ x, float* __restrict__ out) {
    extern __shared__ char smem[];
    const uint32_t sb = smem_u32(smem);
    float* sSsq = reinterpret_cast<float*>(smem + SM_SSQ);
    float* sZ   = reinterpret_cast<float*>(smem + SM_SZ);   // [ni][row][6]
    const int tid = threadIdx.x;

    // ---- load phase: thread = (patch p = tid>>1, half h = tid&1 -> 2 channels)
    {
        const int p  = tid >> 1;
        const int h  = tid & 1;
        const int pi = blockIdx.x * 128 + p;
        const int b   = pi / OHW;
        const int rem = pi - b * OHW;
        const int oy  = rem / OH;
        const int ox  = rem - oy * OH;
        const float* xb = x + (((b * 4 + 2 * h) * 128) + 2 * oy) * 128 + 2 * ox;

        float ssq = 0.f;
        #pragma unroll
        for (int c2 = 0; c2 < 2; c2++) {
            #pragma unroll
            for (int ky2 = 0; ky2 < 2; ky2++) {
                const float* rA = xb + c2 * 16384 + (2 * ky2) * 128;
                float2 a0 = *reinterpret_cast<const float2*>(rA);
                float2 a1 = *reinterpret_cast<const float2*>(rA + 2);
                float2 b0 = *reinterpret_cast<const float2*>(rA + 128);
                float2 b1 = *reinterpret_cast<const float2*>(rA + 130);
                float v[8] = {a0.x, a0.y, a1.x, a1.y, b0.x, b0.y, b1.x, b1.y};
                uint32_t hw[4], lw[4];
                #pragma unroll
                for (int j = 0; j < 4; j++) {
                    float va = v[2 * j], vb = v[2 * j + 1];
                    ssq += va * va + vb * vb;
                    __nv_bfloat16 ah = __float2bfloat16(va);
                    __nv_bfloat16 bh = __float2bfloat16(vb);
                    __nv_bfloat16 al = __float2bfloat16(va - __bfloat162float(ah));
                    __nv_bfloat16 bl = __float2bfloat16(vb - __bfloat162float(bh));
                    __nv_bfloat162 hp = {ah, bh}, lp = {al, bl};
                    hw[j] = *reinterpret_cast<uint32_t*>(&hp);
                    lw[j] = *reinterpret_cast<uint32_t*>(&lp);
                }
                int chunk = h * 4 + c2 * 2 + ky2;
                uint32_t off = SWZ((uint32_t)(p * 128 + chunk * 16));
                *reinterpret_cast<uint4*>(smem + SM_AH + off) = make_uint4(hw[0], hw[1], hw[2], hw[3]);
                *reinterpret_cast<uint4*>(smem + SM_AL + off) = make_uint4(lw[0], lw[1], lw[2], lw[3]);
            }
        }
        ssq += __shfl_xor_sync(0xffffffffu, ssq, 1);
        if (h == 0) sSsq[p] = ssq;
    }

    // ---- stage B (hi/lo) with swizzle ----
    {
        const uint4* bh = reinterpret_cast<const uint4*>(g_Bh);
        const uint4* bl = reinterpret_cast<const uint4*>(g_Bl);
        #pragma unroll
        for (int it = 0; it < 4; it++) {
            int idx = tid + it * 256;
            uint32_t off = SWZ((uint32_t)(idx * 16));
            *reinterpret_cast<uint4*>(smem + SM_BH + off) = bh[idx];
            *reinterpret_cast<uint4*>(smem + SM_BL + off) = bl[idx];
        }
    }
    __syncthreads();

    // ---- GEMM: warp (mi,ni): rows [32mi,32mi+32), cols [64ni,64ni+64) ----
    const int L   = tid & 31;
    const int wid = tid >> 5;
    const int mi  = wid >> 1;
    const int ni  = wid & 1;
    const int Rm  = mi * 32;
    const int Cn  = ni * 64;
    const int g   = L >> 2;
    const int qd  = L & 3;

    const uint32_t aRow = (uint32_t)(Rm + (L & 7) + (((L >> 3) & 1) << 3));
    const uint32_t aCh  = (L >> 4) & 1;
    const uint32_t bRow = (uint32_t)(Cn + (L & 7) + (((L >> 4) & 1) << 3));
    const uint32_t bCh  = (L >> 3) & 1;

    float acc[2][8][4];
    #pragma unroll
    for (int mt = 0; mt < 2; mt++)
        #pragma unroll
        for (int nt = 0; nt < 8; nt++)
            #pragma unroll
            for (int r = 0; r < 4; r++) acc[mt][nt][r] = 0.f;

    #pragma unroll
    for (int k = 0; k < 4; k++) {
        uint32_t ah[2][4], al[2][4];
        #pragma unroll
        for (int mt = 0; mt < 2; mt++) {
            uint32_t off = SWZ((aRow + mt * 16) * 128 + (2 * k + aCh) * 16);
            ldmx4(ah[mt], sb + SM_AH + off);
            ldmx4(al[mt], sb + SM_AL + off);
        }
        #pragma unroll
        for (int bt = 0; bt < 4; bt++) {
            uint32_t off = SWZ((bRow + bt * 16) * 128 + (2 * k + bCh) * 16);
            uint32_t bh[4], bl[4];
            ldmx4(bh, sb + SM_BH + off);
            ldmx4(bl, sb + SM_BL + off);
            #pragma unroll
            for (int mt = 0; mt < 2; mt++)
                #pragma unroll
                for (int n2 = 0; n2 < 2; n2++) {
                    int nt = bt * 2 + n2;
                    mma_bf16(acc[mt][nt], ah[mt], bh + 2 * n2);
                    mma_bf16(acc[mt][nt], ah[mt], bl + 2 * n2);
                    mma_bf16(acc[mt][nt], al[mt], bh + 2 * n2);
                }
        }
    }

    // ---- epilogue: per thread 4 rows; state s = 32ni + 4nt + qd ----
    #pragma unroll
    for (int mt = 0; mt < 2; mt++) {
        #pragma unroll
        for (int rh = 0; rh < 2; rh++) {
            float pr[8];
            #pragma unroll
            for (int nt = 0; nt < 8; nt++) {
                float re = acc[mt][nt][rh * 2 + 0];
                float im = acc[mt][nt][rh * 2 + 1];
                pr[nt] = re * re + im * im;
            }
            float qt = 0.f, z1 = 0.f, z2 = 0.f, z3 = 0.f;
            #pragma unroll
            for (int nt = 0; nt < 8; nt++) {
                qt += pr[nt];
                z1 += (nt & 4) ? -pr[nt] : pr[nt];   // qubit1 <-> s bit4
                z2 += (nt & 2) ? -pr[nt] : pr[nt];   // qubit2 <-> s bit3
                z3 += (nt & 1) ? -pr[nt] : pr[nt];   // qubit3 <-> s bit2
            }
            float z0 = qt;                            // qubit0 sign by ni at merge
            float z4 = (qd & 2) ? -qt : qt;           // qubit4 <-> s bit1
            float z5 = (qd & 1) ? -qt : qt;           // qubit5 <-> s bit0
            #pragma unroll
            for (int o = 1; o <= 2; o <<= 1) {
                z0 += __shfl_xor_sync(0xffffffffu, z0, o);
                z1 += __shfl_xor_sync(0xffffffffu, z1, o);
                z2 += __shfl_xor_sync(0xffffffffu, z2, o);
                z3 += __shfl_xor_sync(0xffffffffu, z3, o);
                z4 += __shfl_xor_sync(0xffffffffu, z4, o);
                z5 += __shfl_xor_sync(0xffffffffu, z5, o);
            }
            if (qd == 0) {
                int row = Rm + mt * 16 + rh * 8 + g;
                float* dst = sZ + (ni * 128 + row) * 6;
                dst[0] = z0; dst[1] = z1; dst[2] = z2;
                dst[3] = z3; dst[4] = z4; dst[5] = z5;
            }
        }
    }
    __syncthreads();

    // ---- merge halves + normalize + store ----
    if (tid < 128) {
        const int row = tid;
        const int pi  = blockIdx.x * 128 + row;
        const int b   = pi / OHW;
        const int rem = pi - b * OHW;
        const float inv = 1.f / sSsq[row];
        const float* p0 = sZ + row * 6;
        const float* p1 = sZ + (128 + row) * 6;
        out[(b * 6 + 0) * OHW + rem] = (p0[0] - p1[0]) * inv;
        #pragma unroll
        for (int w = 1; w < 6; w++)
            out[(b * 6 + w) * OHW + rem] = (p0[w] + p1[w]) * inv;
    }
}

// ----------------------------------------------------------------------------
extern "C" void kernel_launch(void* const* d_in, const int* in_sizes, int n_in,
                              void* d_out, int out_size) {
    const float* x = (const float*)d_in[0];      // (128, 4, 128, 128) f32
    const float* w = (const float*)d_in[1];      // (2, 6, 3) f32
    float* out = (float*)d_out;                  // (128, 6, 63, 63) f32
    (void)in_sizes; (void)n_in; (void)out_size;

    cudaFuncSetAttribute(qconv_kernel, cudaFuncAttributeMaxDynamicSharedMemorySize, SM_TOTAL);
    build_unitary_kernel<<<4, 256>>>(w);
    qconv_kernel<<<NPATCH / 128, 256, SM_TOTAL>>>(x, out);
}